// round 4
// baseline (speedup 1.0000x reference)
#include <cuda_runtime.h>

// Decoder: y_{t+1} = y_t + cutoff * tanh(dt * MLP_b(y_t) / cutoff), per-batch weights.
// B=256 CTAs (one batch each), 256 threads (one hidden unit each), persistent over T.
// Exact ReLU sparsity: rows of the next weight matrix whose input h[k]==0 are skipped
// (deterministic ballot-scan compaction). in/out weights + biases pinned in SMEM.

#define NB 256
#define NC 16
#define NH 256
#define NT 1000
#define TB 8   // output staging depth (NT % TB == 0)

__global__ __launch_bounds__(256, 2)
void decoder_kernel(const float* __restrict__ y0,
                    const float* __restrict__ in_w,    // [B, C, H]
                    const float* __restrict__ in_b,    // [B, H]
                    const float* __restrict__ out_w,   // [B, H, C]
                    const float* __restrict__ out_b,   // [B, C]
                    const float* __restrict__ pw,      // [B, P=2, H, H]  (row = input k)
                    const float* __restrict__ pb,      // [B, 2, H]
                    const float* __restrict__ cutoff,  // [1]
                    float* __restrict__ out)           // [B, C, T]
{
    __shared__ float  in_s[NC * NH];     // [c][i]
    __shared__ float  out_s[NH * NC];    // [k][c]
    __shared__ float2 act[NH];           // compacted (h, byte_offset-as-float-bits)
    __shared__ int    cnt_s[8];
    __shared__ float  ys[NC];
    __shared__ float  po_s[256];         // out-layer partials [g][c]
    __shared__ float  stage[NC][TB];     // output staging

    const int b    = blockIdx.x;
    const int i    = threadIdx.x;
    const int lane = i & 31;
    const int wid  = i >> 5;

    // ---- preload per-batch small weights into SMEM (gmem traffic once) ----
    const float* inwb  = in_w  + (size_t)b * NC * NH;
    const float* outwb = out_w + (size_t)b * NH * NC;

#pragma unroll
    for (int c = 0; c < NC; c++)
        in_s[c * NH + i] = inwb[c * NH + i];

#pragma unroll
    for (int q = 0; q < 4; q++) {
        float4 v = *reinterpret_cast<const float4*>(outwb + i * NC + q * 4);
        *reinterpret_cast<float4*>(&out_s[i * NC + q * 4]) = v;
    }

    const float bin = in_b[(size_t)b * NH + i];
    const float bp0 = pb[(size_t)b * 2 * NH + i];
    const float bp1 = pb[(size_t)b * 2 * NH + NH + i];
    const float ob  = (i < NC) ? out_b[(size_t)b * NC + i] : 0.f;
    const float cut = cutoff[0];
    const float dt  = 1e-6f;

    if (i < NC) ys[i] = y0[(size_t)b * NC + i];

    const char* pw0 = reinterpret_cast<const char*>(pw + (size_t)b * 2 * NH * NH);
    const char* pw1 = pw0 + (size_t)NH * NH * sizeof(float);
    float* outg = out + (size_t)b * NC * NT;

    int na = 0;  // active count, identical across threads after compact()

    // Deterministic compaction of nonzero h into act[] (order: warp-major, lane order).
    auto compact = [&](float hv) {
        bool nz = hv > 0.f;
        unsigned bal = __ballot_sync(0xffffffffu, nz);
        if (lane == 0) cnt_s[wid] = __popc(bal);
        __syncthreads();                       // also protects act[] (all reads done)
        int base = 0, tot = 0;
#pragma unroll
        for (int w = 0; w < 8; w++) {
            int cc = cnt_s[w];
            tot += cc;
            if (w < wid) base += cc;
        }
        na = tot;
        if (nz) {
            int pos = base + __popc(bal & ((1u << lane) - 1u));
            act[pos] = make_float2(hv, __int_as_float(i << 10));  // byte off = k*H*4
        }
        __syncthreads();
    };

    // Sparse matvec: acc += sum over active k of h[k] * W[k][i]; W rows coalesced.
    auto dotp = [&](const char* wbase, float bias) -> float {
        const char* bi = wbase + (size_t)(i * 4);
        float a = bias;
        int m = 0;
        const int n8 = na & ~7;
        for (; m < n8; m += 8) {
            float2 e0 = act[m + 0], e1 = act[m + 1], e2 = act[m + 2], e3 = act[m + 3];
            float2 e4 = act[m + 4], e5 = act[m + 5], e6 = act[m + 6], e7 = act[m + 7];
            float w0 = *reinterpret_cast<const float*>(bi + __float_as_int(e0.y));
            float w1 = *reinterpret_cast<const float*>(bi + __float_as_int(e1.y));
            float w2 = *reinterpret_cast<const float*>(bi + __float_as_int(e2.y));
            float w3 = *reinterpret_cast<const float*>(bi + __float_as_int(e3.y));
            float w4 = *reinterpret_cast<const float*>(bi + __float_as_int(e4.y));
            float w5 = *reinterpret_cast<const float*>(bi + __float_as_int(e5.y));
            float w6 = *reinterpret_cast<const float*>(bi + __float_as_int(e6.y));
            float w7 = *reinterpret_cast<const float*>(bi + __float_as_int(e7.y));
            a = fmaf(e0.x, w0, a);
            a = fmaf(e1.x, w1, a);
            a = fmaf(e2.x, w2, a);
            a = fmaf(e3.x, w3, a);
            a = fmaf(e4.x, w4, a);
            a = fmaf(e5.x, w5, a);
            a = fmaf(e6.x, w6, a);
            a = fmaf(e7.x, w7, a);
        }
        for (; m < na; m++) {
            float2 e = act[m];
            a = fmaf(e.x, *reinterpret_cast<const float*>(bi + __float_as_int(e.y)), a);
        }
        return a;
    };

    __syncthreads();

    for (int t = 0; t < NT; t++) {
        // ---- input layer (all from SMEM) ----
        float acc = bin;
#pragma unroll
        for (int c = 0; c < NC; c++)
            acc = fmaf(ys[c], in_s[c * NH + i], acc);
        compact(fmaxf(acc, 0.f));

        // ---- two prop layers (sparse gmem rows) ----
        compact(fmaxf(dotp(pw0, bp0), 0.f));
        compact(fmaxf(dotp(pw1, bp1), 0.f));

        // ---- output layer (from SMEM, sparse over k) ----
        {
            int c = i & 15, g = i >> 4;
            float p = 0.f;
            for (int m = g; m < na; m += 16) {
                float2 e = act[m];
                // byte off = k<<10  ->  out_s index k*16 + c = (off>>6) + c
                p = fmaf(e.x, out_s[(__float_as_int(e.y) >> 6) + c], p);
            }
            po_s[i] = p;
        }
        __syncthreads();

        if (i < NC) {
            float f = ob;
#pragma unroll
            for (int g = 0; g < 16; g++) f += po_s[g * 16 + i];
            float yn = ys[i] + cut * tanhf(dt * f / cut);
            ys[i] = yn;
            stage[i][t & (TB - 1)] = yn;
        }
        __syncthreads();

        // coalesced flush every TB steps
        if ((t & (TB - 1)) == (TB - 1) && i < NC * TB) {
            int c = i >> 3, u = i & 7;
            outg[c * NT + (t - (TB - 1)) + u] = stage[c][u];
        }
    }
}

extern "C" void kernel_launch(void* const* d_in, const int* in_sizes, int n_in,
                              void* d_out, int out_size)
{
    (void)in_sizes; (void)n_in; (void)out_size;
    decoder_kernel<<<NB, 256>>>(
        (const float*)d_in[0],   // y0
        (const float*)d_in[1],   // in_weight
        (const float*)d_in[2],   // in_bias
        (const float*)d_in[3],   // out_weight
        (const float*)d_in[4],   // out_bias
        (const float*)d_in[5],   // prop_weight
        (const float*)d_in[6],   // prop_bias
        (const float*)d_in[7],   // cutoff
        (float*)d_out);
}

// round 5
// speedup vs baseline: 1.6270x; 1.6270x over previous
#include <cuda_runtime.h>

// Decoder: y_{t+1} = y_t + cutoff * tanh(dt * MLP_b(y_t) / cutoff), per-batch weights.
// 256 CTAs (one batch), 256 threads, persistent over T=1000 steps.
// Exact ReLU sparsity: skip weight rows whose input h[k]==0 (ballot compaction).
// Sparse matvec reads rows via LDG.128 float4, 4 outputs per thread, unroll-8
// (32 wavefronts in flight per warp). in/out weights + biases pinned in SMEM.

#define NB 256
#define NC 16
#define NH 256
#define NT 1000
#define TB 8   // output staging depth (NT % TB == 0)

__global__ __launch_bounds__(256, 2)
void decoder_kernel(const float* __restrict__ y0,
                    const float* __restrict__ in_w,    // [B, C, H]
                    const float* __restrict__ in_b,    // [B, H]
                    const float* __restrict__ out_w,   // [B, H, C]
                    const float* __restrict__ out_b,   // [B, C]
                    const float* __restrict__ pw,      // [B, 2, H, H] (row = input k)
                    const float* __restrict__ pb,      // [B, 2, H]
                    const float* __restrict__ cutoff,  // [1]
                    float* __restrict__ out)           // [B, C, T]
{
    __shared__ float  in_s[NC * NH];     // [c][i]
    __shared__ float  out_s[NH * NC];    // [k][c]
    __shared__ float2 act[NH];           // compacted (h, row byte-offset as bits)
    __shared__ int    cnt_s[8];
    __shared__ float  ys[NC];
    __shared__ float  po4[4 * NH];       // [group g][output i] partials (float4 writes)
    __shared__ float  po_s[256];         // out-layer partials [g16][c]
    __shared__ float  stage[NC][TB];

    const int b    = blockIdx.x;
    const int i    = threadIdx.x;
    const int lane = i & 31;
    const int wid  = i >> 5;
    const int g    = i >> 6;   // row group 0..3
    const int o    = i & 63;   // output quad index -> outputs 4o..4o+3

    // ---- preload per-batch small weights into SMEM ----
    const float* inwb  = in_w  + (size_t)b * NC * NH;
    const float* outwb = out_w + (size_t)b * NH * NC;

#pragma unroll
    for (int c = 0; c < NC; c++)
        in_s[c * NH + i] = inwb[c * NH + i];

#pragma unroll
    for (int q = 0; q < 4; q++) {
        float4 v = *reinterpret_cast<const float4*>(outwb + i * NC + q * 4);
        *reinterpret_cast<float4*>(&out_s[i * NC + q * 4]) = v;
    }

    const float bin = in_b[(size_t)b * NH + i];
    const float bp0 = pb[(size_t)b * 2 * NH + i];
    const float bp1 = pb[(size_t)b * 2 * NH + NH + i];
    const float ob  = (i < NC) ? out_b[(size_t)b * NC + i] : 0.f;
    const float cut = cutoff[0];
    const float dt  = 1e-6f;

    if (i < NC) ys[i] = y0[(size_t)b * NC + i];

    const char* pw0 = reinterpret_cast<const char*>(pw + (size_t)b * 2 * NH * NH);
    const char* pw1 = pw0 + (size_t)NH * NH * sizeof(float);
    float* outg = out + (size_t)b * NC * NT;

    int na = 0;  // active count (uniform across CTA after compact)

    // Deterministic compaction of nonzero h into act[] (warp-major, lane order).
    auto compact = [&](float hv) {
        bool nz = hv > 0.f;
        unsigned bal = __ballot_sync(0xffffffffu, nz);
        if (lane == 0) cnt_s[wid] = __popc(bal);
        __syncthreads();
        int base = 0, tot = 0;
#pragma unroll
        for (int w = 0; w < 8; w++) {
            int cc = cnt_s[w];
            tot += cc;
            if (w < wid) base += cc;
        }
        na = tot;
        if (nz) {
            int pos = base + __popc(bal & ((1u << lane) - 1u));
            act[pos] = make_float2(hv, __int_as_float(i << 10));  // byte off = k*H*4
        }
        __syncthreads();
    };

    // Sparse matvec, 4 outputs/thread: acc[c] += sum over m≡g (mod 4) of
    // h[m] * W[row(m)][4o+c], one LDG.128 per (thread,row).
    auto dotp4 = [&](const char* wbase) -> float4 {
        const char* bo = wbase + (size_t)(o * 16);
        float4 a = make_float4(0.f, 0.f, 0.f, 0.f);
        int m = g;
        for (; m + 28 < na; m += 32) {
            float2 e0 = act[m +  0], e1 = act[m +  4], e2 = act[m +  8], e3 = act[m + 12];
            float2 e4 = act[m + 16], e5 = act[m + 20], e6 = act[m + 24], e7 = act[m + 28];
            float4 w0 = *reinterpret_cast<const float4*>(bo + __float_as_int(e0.y));
            float4 w1 = *reinterpret_cast<const float4*>(bo + __float_as_int(e1.y));
            float4 w2 = *reinterpret_cast<const float4*>(bo + __float_as_int(e2.y));
            float4 w3 = *reinterpret_cast<const float4*>(bo + __float_as_int(e3.y));
            float4 w4 = *reinterpret_cast<const float4*>(bo + __float_as_int(e4.y));
            float4 w5 = *reinterpret_cast<const float4*>(bo + __float_as_int(e5.y));
            float4 w6 = *reinterpret_cast<const float4*>(bo + __float_as_int(e6.y));
            float4 w7 = *reinterpret_cast<const float4*>(bo + __float_as_int(e7.y));
            a.x = fmaf(e0.x, w0.x, a.x); a.y = fmaf(e0.x, w0.y, a.y);
            a.z = fmaf(e0.x, w0.z, a.z); a.w = fmaf(e0.x, w0.w, a.w);
            a.x = fmaf(e1.x, w1.x, a.x); a.y = fmaf(e1.x, w1.y, a.y);
            a.z = fmaf(e1.x, w1.z, a.z); a.w = fmaf(e1.x, w1.w, a.w);
            a.x = fmaf(e2.x, w2.x, a.x); a.y = fmaf(e2.x, w2.y, a.y);
            a.z = fmaf(e2.x, w2.z, a.z); a.w = fmaf(e2.x, w2.w, a.w);
            a.x = fmaf(e3.x, w3.x, a.x); a.y = fmaf(e3.x, w3.y, a.y);
            a.z = fmaf(e3.x, w3.z, a.z); a.w = fmaf(e3.x, w3.w, a.w);
            a.x = fmaf(e4.x, w4.x, a.x); a.y = fmaf(e4.x, w4.y, a.y);
            a.z = fmaf(e4.x, w4.z, a.z); a.w = fmaf(e4.x, w4.w, a.w);
            a.x = fmaf(e5.x, w5.x, a.x); a.y = fmaf(e5.x, w5.y, a.y);
            a.z = fmaf(e5.x, w5.z, a.z); a.w = fmaf(e5.x, w5.w, a.w);
            a.x = fmaf(e6.x, w6.x, a.x); a.y = fmaf(e6.x, w6.y, a.y);
            a.z = fmaf(e6.x, w6.z, a.z); a.w = fmaf(e6.x, w6.w, a.w);
            a.x = fmaf(e7.x, w7.x, a.x); a.y = fmaf(e7.x, w7.y, a.y);
            a.z = fmaf(e7.x, w7.z, a.z); a.w = fmaf(e7.x, w7.w, a.w);
        }
        for (; m < na; m += 4) {
            float2 e = act[m];
            float4 w = *reinterpret_cast<const float4*>(bo + __float_as_int(e.y));
            a.x = fmaf(e.x, w.x, a.x); a.y = fmaf(e.x, w.y, a.y);
            a.z = fmaf(e.x, w.z, a.z); a.w = fmaf(e.x, w.w, a.w);
        }
        return a;
    };

    // Dense prop layer: dotp4 -> float4 smem write -> cross-group reduce -> relu -> compact
    auto prop_layer = [&](const char* wbase, float bias) {
        float4 a = dotp4(wbase);
        *reinterpret_cast<float4*>(&po4[g * NH + o * 4]) = a;
        __syncthreads();
        // po4 flat index g*256 + (o*4+c) == g*256 + i  => output i
        float h = bias + po4[i] + po4[NH + i] + po4[2 * NH + i] + po4[3 * NH + i];
        compact(fmaxf(h, 0.f));
    };

    __syncthreads();

    for (int t = 0; t < NT; t++) {
        // ---- input layer (all SMEM) ----
        float acc = bin;
#pragma unroll
        for (int c = 0; c < NC; c++)
            acc = fmaf(ys[c], in_s[c * NH + i], acc);
        compact(fmaxf(acc, 0.f));

        // ---- two prop layers (sparse gmem rows, float4) ----
        prop_layer(pw0, bp0);
        prop_layer(pw1, bp1);

        // ---- output layer (SMEM, sparse over k) ----
        {
            int c = i & 15, g16 = i >> 4;
            float p = 0.f;
            for (int m = g16; m < na; m += 16) {
                float2 e = act[m];
                // byte off = k<<10 -> out_s index k*16 + c = (off>>6) + c
                p = fmaf(e.x, out_s[(__float_as_int(e.y) >> 6) + c], p);
            }
            po_s[i] = p;
        }
        __syncthreads();

        if (i < NC) {
            float f = ob;
#pragma unroll
            for (int g16 = 0; g16 < 16; g16++) f += po_s[g16 * 16 + i];
            float yn = ys[i] + cut * tanhf(dt * f / cut);
            ys[i] = yn;
            stage[i][t & (TB - 1)] = yn;
        }
        __syncthreads();

        // coalesced flush every TB steps
        if ((t & (TB - 1)) == (TB - 1) && i < NC * TB) {
            int c = i >> 3, u = i & 7;
            outg[c * NT + (t - (TB - 1)) + u] = stage[c][u];
        }
    }
}

extern "C" void kernel_launch(void* const* d_in, const int* in_sizes, int n_in,
                              void* d_out, int out_size)
{
    (void)in_sizes; (void)n_in; (void)out_size;
    decoder_kernel<<<NB, 256>>>(
        (const float*)d_in[0],   // y0
        (const float*)d_in[1],   // in_weight
        (const float*)d_in[2],   // in_bias
        (const float*)d_in[3],   // out_weight
        (const float*)d_in[4],   // out_bias
        (const float*)d_in[5],   // prop_weight
        (const float*)d_in[6],   // prop_bias
        (const float*)d_in[7],   // cutoff
        (float*)d_out);
}